// round 3
// baseline (speedup 1.0000x reference)
#include <cuda_runtime.h>
#include <math.h>

// Problem constants (fixed shapes for this problem instance)
#define BATCH   2
#define SEQ     2048
#define CDIM    2048
#define NHEAD   16
#define NKV     4
#define HDIM    128
#define MROWS   (BATCH * SEQ)          // 4096
#define KVDIM   (NKV * HDIM)           // 512

// GEMM tiling
#define BM 128
#define BN 128
#define BK 8
#define TM 8
#define TN 8
// threads per block = (BM/TM)*(BN/TN) = 256

// ---------------------------------------------------------------------------
// Static device scratch (allocation-free rule: __device__ globals)
// ---------------------------------------------------------------------------
__device__ float g_q[(size_t)MROWS * CDIM];            // 32 MB   [B*T, 16*128]
__device__ float g_k[(size_t)MROWS * KVDIM];           // 8 MB    [B*T, 4*128]
__device__ float g_v[(size_t)MROWS * KVDIM];           // 8 MB
__device__ float g_s[(size_t)BATCH * NHEAD * SEQ * SEQ]; // 537 MB  scores per (b,h)
__device__ float g_att[(size_t)MROWS * CDIM];          // 32 MB   attention out

// ---------------------------------------------------------------------------
// Core NT GEMM tile: C[BM x BN] = alpha * A[BM x K] * B[BN x K]^T
// A row-major (lda), B row-major (ldb), C row-major (ldc).
// Requires: M % BM == 0, N % BN == 0, K % BK == 0, lda/ldb/k0 4-float aligned.
// ---------------------------------------------------------------------------
__device__ __forceinline__ void gemm_core_nt(
    const float* __restrict__ A, int lda,
    const float* __restrict__ B, int ldb,
    float* __restrict__ C, int ldc,
    int K, float alpha)
{
    __shared__ float As[BK][BM];
    __shared__ float Bs[BK][BN];

    const int tid  = threadIdx.x;
    const int tx   = tid & 15;        // N sub-tile index
    const int ty   = tid >> 4;        // M sub-tile index
    const int lrow = tid >> 1;        // 0..127  (row to load)
    const int lcol = (tid & 1) << 2;  // 0 or 4  (col group to load)

    const float* Ap = A + (size_t)blockIdx.y * BM * lda + (size_t)lrow * lda + lcol;
    const float* Bp = B + (size_t)blockIdx.x * BN * ldb + (size_t)lrow * ldb + lcol;

    float acc[TM][TN];
#pragma unroll
    for (int i = 0; i < TM; i++)
#pragma unroll
        for (int j = 0; j < TN; j++) acc[i][j] = 0.0f;

    float4 a4 = *reinterpret_cast<const float4*>(Ap);
    float4 b4 = *reinterpret_cast<const float4*>(Bp);

    for (int k0 = 0; k0 < K; k0 += BK) {
        As[lcol + 0][lrow] = a4.x; As[lcol + 1][lrow] = a4.y;
        As[lcol + 2][lrow] = a4.z; As[lcol + 3][lrow] = a4.w;
        Bs[lcol + 0][lrow] = b4.x; Bs[lcol + 1][lrow] = b4.y;
        Bs[lcol + 2][lrow] = b4.z; Bs[lcol + 3][lrow] = b4.w;
        __syncthreads();

        if (k0 + BK < K) {  // register prefetch of next tile
            a4 = *reinterpret_cast<const float4*>(Ap + k0 + BK);
            b4 = *reinterpret_cast<const float4*>(Bp + k0 + BK);
        }

#pragma unroll
        for (int kk = 0; kk < BK; kk++) {
            float ar[TM], br[TN];
#pragma unroll
            for (int i = 0; i < TM; i++) ar[i] = As[kk][ty * TM + i];
#pragma unroll
            for (int j = 0; j < TN; j++) br[j] = Bs[kk][tx * TN + j];
#pragma unroll
            for (int i = 0; i < TM; i++)
#pragma unroll
                for (int j = 0; j < TN; j++)
                    acc[i][j] = fmaf(ar[i], br[j], acc[i][j]);
        }
        __syncthreads();
    }

    float* Cp = C + (size_t)blockIdx.y * BM * ldc + (size_t)blockIdx.x * BN;
#pragma unroll
    for (int i = 0; i < TM; i++) {
        float* crow = Cp + (size_t)(ty * TM + i) * ldc + tx * TN;
#pragma unroll
        for (int j = 0; j < TN; j += 4) {
            float4 v4 = make_float4(acc[i][j] * alpha, acc[i][j + 1] * alpha,
                                    acc[i][j + 2] * alpha, acc[i][j + 3] * alpha);
            *reinterpret_cast<float4*>(crow + j) = v4;
        }
    }
}

// ---------------------------------------------------------------------------
// Core NN GEMM tile: C[BM x 128] = A[BM x K] * B[K x 128]
// Used for P @ V (N = HDIM = 128, so a single BN tile; blockIdx.x unused).
// ---------------------------------------------------------------------------
__device__ __forceinline__ void gemm_core_nn(
    const float* __restrict__ A, int lda,
    const float* __restrict__ B, int ldb,
    float* __restrict__ C, int ldc,
    int K)
{
    __shared__ float As[BK][BM];
    __shared__ float Bs[BK][BN];

    const int tid  = threadIdx.x;
    const int tx   = tid & 15;
    const int ty   = tid >> 4;
    const int lrow = tid >> 1;
    const int lcol = (tid & 1) << 2;
    const int brow = tid >> 5;         // 0..7
    const int bcol = (tid & 31) << 2;  // 0..124

    const float* Ap = A + (size_t)blockIdx.y * BM * lda + (size_t)lrow * lda + lcol;
    const float* Bp = B + (size_t)brow * ldb + bcol;

    float acc[TM][TN];
#pragma unroll
    for (int i = 0; i < TM; i++)
#pragma unroll
        for (int j = 0; j < TN; j++) acc[i][j] = 0.0f;

    float4 a4 = *reinterpret_cast<const float4*>(Ap);
    float4 b4 = *reinterpret_cast<const float4*>(Bp);

    for (int k0 = 0; k0 < K; k0 += BK) {
        As[lcol + 0][lrow] = a4.x; As[lcol + 1][lrow] = a4.y;
        As[lcol + 2][lrow] = a4.z; As[lcol + 3][lrow] = a4.w;
        *reinterpret_cast<float4*>(&Bs[brow][bcol]) = b4;
        __syncthreads();

        if (k0 + BK < K) {
            a4 = *reinterpret_cast<const float4*>(Ap + k0 + BK);
            b4 = *reinterpret_cast<const float4*>(Bp + (size_t)(k0 + BK) * ldb);
        }

#pragma unroll
        for (int kk = 0; kk < BK; kk++) {
            float ar[TM], br[TN];
#pragma unroll
            for (int i = 0; i < TM; i++) ar[i] = As[kk][ty * TM + i];
#pragma unroll
            for (int j = 0; j < TN; j++) br[j] = Bs[kk][tx * TN + j];
#pragma unroll
            for (int i = 0; i < TM; i++)
#pragma unroll
                for (int j = 0; j < TN; j++)
                    acc[i][j] = fmaf(ar[i], br[j], acc[i][j]);
        }
        __syncthreads();
    }

    float* Cp = C + (size_t)blockIdx.y * BM * ldc;
#pragma unroll
    for (int i = 0; i < TM; i++) {
        float* crow = Cp + (size_t)(ty * TM + i) * ldc + tx * TN;
#pragma unroll
        for (int j = 0; j < TN; j += 4) {
            float4 v4 = make_float4(acc[i][j], acc[i][j + 1], acc[i][j + 2], acc[i][j + 3]);
            *reinterpret_cast<float4*>(crow + j) = v4;
        }
    }
}

// ---------------------------------------------------------------------------
// Projection kernels (x @ W^T)
// ---------------------------------------------------------------------------
__global__ __launch_bounds__(256) void k_proj_q(const float* __restrict__ x,
                                                const float* __restrict__ W) {
    gemm_core_nt(x, CDIM, W, CDIM, g_q, CDIM, CDIM, 1.0f);
}
__global__ __launch_bounds__(256) void k_proj_k(const float* __restrict__ x,
                                                const float* __restrict__ W) {
    gemm_core_nt(x, CDIM, W, CDIM, g_k, KVDIM, CDIM, 1.0f);
}
__global__ __launch_bounds__(256) void k_proj_v(const float* __restrict__ x,
                                                const float* __restrict__ W) {
    gemm_core_nt(x, CDIM, W, CDIM, g_v, KVDIM, CDIM, 1.0f);
}
__global__ __launch_bounds__(256) void k_oproj(const float* __restrict__ Wo,
                                               float* __restrict__ out) {
    gemm_core_nt(g_att, CDIM, Wo, CDIM, out, CDIM, CDIM, 1.0f);
}

// ---------------------------------------------------------------------------
// RoPE (Llama half-rotation), applied in-place to q and k.
// Tables computed in fp64 so fast-math can't hurt accuracy at ang ~ 2048 rad.
// grid = B*T blocks, 256 threads.
// ---------------------------------------------------------------------------
__global__ void k_rope(const int* __restrict__ start_pos) {
    __shared__ float cs[HDIM / 2], sn[HDIM / 2];
    const int bt  = blockIdx.x;            // b*SEQ + t
    const int t   = bt & (SEQ - 1);
    const int tid = threadIdx.x;

    if (tid < HDIM / 2) {
        double inv = pow(10000.0, -(double)(2 * tid) / (double)HDIM);
        double ang = (double)(t + start_pos[0]) * inv;
        cs[tid] = (float)cos(ang);
        sn[tid] = (float)sin(ang);
    }
    __syncthreads();

    float* qrow = g_q + (size_t)bt * CDIM;
    for (int idx = tid; idx < NHEAD * (HDIM / 2); idx += blockDim.x) {
        int h = idx >> 6, i = idx & 63;
        float x1 = qrow[h * HDIM + i];
        float x2 = qrow[h * HDIM + i + 64];
        qrow[h * HDIM + i]      = x1 * cs[i] - x2 * sn[i];
        qrow[h * HDIM + i + 64] = x2 * cs[i] + x1 * sn[i];
    }
    float* krow = g_k + (size_t)bt * KVDIM;
    for (int idx = tid; idx < NKV * (HDIM / 2); idx += blockDim.x) {
        int h = idx >> 6, i = idx & 63;
        float x1 = krow[h * HDIM + i];
        float x2 = krow[h * HDIM + i + 64];
        krow[h * HDIM + i]      = x1 * cs[i] - x2 * sn[i];
        krow[h * HDIM + i + 64] = x2 * cs[i] + x1 * sn[i];
    }
}

// ---------------------------------------------------------------------------
// Scores: S[z][s][t] = scale * q_h[s,:] . k_g[t,:]   (z = b*16 + h, g = h/4)
// grid (16, 16, 32)
// ---------------------------------------------------------------------------
__global__ __launch_bounds__(256) void k_qk() {
    const int z = blockIdx.z;
    const int b = z >> 4;
    const int h = z & 15;
    const int g = h >> 2;
    const float* A = g_q + (size_t)b * SEQ * CDIM + (size_t)h * HDIM;
    const float* B = g_k + (size_t)b * SEQ * KVDIM + (size_t)g * HDIM;
    float* C = g_s + (size_t)z * SEQ * SEQ;
    gemm_core_nt(A, CDIM, B, KVDIM, C, SEQ, HDIM, 0.08838834764831845f); // 1/sqrt(128)
}

// ---------------------------------------------------------------------------
// Row softmax over S (rows of length SEQ=2048). Warp-per-row, values held in
// registers (64/lane): 1 read + 1 write of the 537 MB buffer.
// grid = (B*NHEAD*SEQ)/8 blocks, 256 threads (8 warps).
// ---------------------------------------------------------------------------
__global__ __launch_bounds__(256) void k_softmax() {
    const int row  = blockIdx.x * 8 + (threadIdx.x >> 5);
    const int lane = threadIdx.x & 31;
    float* p = g_s + (size_t)row * SEQ;

    float vals[64];
    float m = -INFINITY;
#pragma unroll
    for (int i = 0; i < 64; i++) {
        vals[i] = p[lane + i * 32];
        m = fmaxf(m, vals[i]);
    }
#pragma unroll
    for (int o = 16; o > 0; o >>= 1) m = fmaxf(m, __shfl_xor_sync(0xFFFFFFFFu, m, o));

    float s = 0.0f;
#pragma unroll
    for (int i = 0; i < 64; i++) {
        vals[i] = expf(vals[i] - m);
        s += vals[i];
    }
#pragma unroll
    for (int o = 16; o > 0; o >>= 1) s += __shfl_xor_sync(0xFFFFFFFFu, s, o);

    const float inv = 1.0f / s;
#pragma unroll
    for (int i = 0; i < 64; i++) p[lane + i * 32] = vals[i] * inv;
}

// ---------------------------------------------------------------------------
// O_h = P @ V_g : per (b,h), [SEQ x SEQ] @ [SEQ x 128] -> g_att at head slot h
// grid (1, 16, 32)
// ---------------------------------------------------------------------------
__global__ __launch_bounds__(256) void k_pv() {
    const int z = blockIdx.z;
    const int b = z >> 4;
    const int h = z & 15;
    const int g = h >> 2;
    const float* A = g_s + (size_t)z * SEQ * SEQ;
    const float* B = g_v + (size_t)b * SEQ * KVDIM + (size_t)g * HDIM;
    float* C = g_att + (size_t)b * SEQ * CDIM + (size_t)h * HDIM;
    gemm_core_nn(A, SEQ, B, KVDIM, C, CDIM, SEQ);
}

// ---------------------------------------------------------------------------
// Entry point
// ---------------------------------------------------------------------------
extern "C" void kernel_launch(void* const* d_in, const int* in_sizes, int n_in,
                              void* d_out, int out_size) {
    const float* x  = (const float*)d_in[0];
    const float* Wq = (const float*)d_in[1];
    const float* Wk = (const float*)d_in[2];
    const float* Wv = (const float*)d_in[3];
    const float* Wo = (const float*)d_in[4];
    const int*   sp = (const int*)d_in[5];
    float* out = (float*)d_out;

    // QKV projections
    k_proj_q<<<dim3(CDIM / BN, MROWS / BM), 256>>>(x, Wq);   // (16, 32)
    k_proj_k<<<dim3(KVDIM / BN, MROWS / BM), 256>>>(x, Wk);  // (4, 32)
    k_proj_v<<<dim3(KVDIM / BN, MROWS / BM), 256>>>(x, Wv);  // (4, 32)

    // RoPE on q and k
    k_rope<<<MROWS, 256>>>(sp);

    // Attention: scores -> softmax -> PV
    k_qk<<<dim3(SEQ / BN, SEQ / BM, BATCH * NHEAD), 256>>>();
    k_softmax<<<(BATCH * NHEAD * SEQ) / 8, 256>>>();
    k_pv<<<dim3(1, SEQ / BM, BATCH * NHEAD), 256>>>();

    // Output projection
    k_oproj<<<dim3(CDIM / BN, MROWS / BM), 256>>>(Wo, out);
}